// round 8
// baseline (speedup 1.0000x reference)
#include <cuda_runtime.h>
#include <cstdint>
#include <cstddef>

#define Nn 8192
#define Kk 64
#define RR 64                  // base top-R per spark row
#define HASHSZ 4096
#define LISTCAP 2432
#define BCAP 128               // per-spark-row bucket capacity
#define CAND (RR + BCAP)

// ---------------------------------------------------------------------------
__device__ float g_s[Nn];
__device__ unsigned long long g_top[Kk][RR];

__device__ __forceinline__ unsigned valkey(float v) {
    return ((v > 0.f) ? __float_as_uint(v) : 0u) + 1u;
}
__device__ __forceinline__ unsigned long long pack64(unsigned key, int col) {
    return ((unsigned long long)key << 32) | (unsigned)(~(unsigned)col);
}
__device__ __forceinline__ int key_idx(unsigned long long k) {
    return (int)(~(unsigned)k);
}

// ---------------------------------------------------------------------------
// Prep kernel: blocks 0..63 compute base top-64 of row spark_pos[b] first,
// then ALL blocks do warp-per-row GEMV + decay-copy.
// ---------------------------------------------------------------------------
__global__ void __launch_bounds__(1024) prep_kernel(
    const float* __restrict__ W,
    const float* __restrict__ s_in,
    const float* __restrict__ noise,
    const int*   __restrict__ spark_pos,
    float*       __restrict__ Wout)
{
    __shared__ unsigned long long wl[32][RR];
    const int tid  = threadIdx.x;
    const int lane = tid & 31;
    const int wid  = tid >> 5;

    if (blockIdx.x < Kk) {
        const int row = spark_pos[blockIdx.x];
        const float4* r4 = reinterpret_cast<const float4*>(W + (size_t)row * Nn);
        const int cbase = (wid << 8) + (lane << 3);
        float4 a = __ldg(&r4[cbase >> 2]);
        float4 b = __ldg(&r4[(cbase >> 2) + 1]);
        unsigned k0 = valkey(a.x), k1 = valkey(a.y), k2 = valkey(a.z), k3 = valkey(a.w);
        unsigned k4 = valkey(b.x), k5 = valkey(b.y), k6 = valkey(b.z), k7 = valkey(b.w);

        for (int p = 0; p < RR; ++p) {
            unsigned bk = k0; int bj = 0;
            if (k1 > bk) { bk = k1; bj = 1; }
            if (k2 > bk) { bk = k2; bj = 2; }
            if (k3 > bk) { bk = k3; bj = 3; }
            if (k4 > bk) { bk = k4; bj = 4; }
            if (k5 > bk) { bk = k5; bj = 5; }
            if (k6 > bk) { bk = k6; bj = 6; }
            if (k7 > bk) { bk = k7; bj = 7; }
            unsigned kmax = __reduce_max_sync(0xFFFFFFFFu, bk);
            unsigned cand = (bk == kmax) ? (unsigned)(cbase + bj) : 0xFFFFFFFFu;
            unsigned cmin = __reduce_min_sync(0xFFFFFFFFu, cand);
            if (lane == 0) wl[wid][p] = pack64(kmax, (int)cmin);
            int rel = (int)cmin - cbase;
            if (rel >= 0 && rel < 8) {
                if (rel == 0) k0 = 0; if (rel == 1) k1 = 0;
                if (rel == 2) k2 = 0; if (rel == 3) k3 = 0;
                if (rel == 4) k4 = 0; if (rel == 5) k5 = 0;
                if (rel == 6) k6 = 0; if (rel == 7) k7 = 0;
            }
        }
        __syncthreads();
        if (wid == 0) {
            int head = 0;
            for (int p = 0; p < RR; ++p) {
                unsigned long long cur = (head < RR) ? wl[lane][head] : 0ull;
                unsigned hi = (unsigned)(cur >> 32);
                unsigned kmax = __reduce_max_sync(0xFFFFFFFFu, hi);
                unsigned lo = (hi == kmax) ? (unsigned)cur : 0u;
                unsigned lomax = __reduce_max_sync(0xFFFFFFFFu, lo);
                if (hi == kmax && (unsigned)cur == lomax) head++;
                if (lane == 0)
                    g_top[blockIdx.x][p] = ((unsigned long long)kmax << 32) | lomax;
            }
        }
        __syncthreads();
    }

    const int gw = blockIdx.x * 32 + wid;
    if (gw < Nn) {
        const float4* wrow  = reinterpret_cast<const float4*>(W    + (size_t)gw * Nn);
        float4*       worow = reinterpret_cast<float4*>      (Wout + (size_t)gw * Nn);
        const float4* s4    = reinterpret_cast<const float4*>(s_in);
        float acc = 0.f;
        #pragma unroll 8
        for (int k = lane; k < Nn / 4; k += 32) {
            float4 w  = __ldcs(&wrow[k]);
            float4 sv = __ldg(&s4[k]);
            acc += w.x * (sv.x * 0.95f) + w.y * (sv.y * 0.95f)
                 + w.z * (sv.z * 0.95f) + w.w * (sv.w * 0.95f);
            float4 o;
            o.x = fminf(fmaxf(w.x * 0.999f, -2.f), 2.f);
            o.y = fminf(fmaxf(w.y * 0.999f, -2.f), 2.f);
            o.z = fminf(fmaxf(w.z * 0.999f, -2.f), 2.f);
            o.w = fminf(fmaxf(w.w * 0.999f, -2.f), 2.f);
            __stcs(&worow[k], o);
        }
        #pragma unroll
        for (int off = 16; off; off >>= 1)
            acc += __shfl_xor_sync(0xFFFFFFFFu, acc, off);
        if (lane == 0) {
            float z = acc + 0.05f * noise[gw];
            g_s[gw] = 1.0f / (1.0f + expf(-z));
        }
    }
}

// ---------------------------------------------------------------------------
// Scan shared memory
// ---------------------------------------------------------------------------
struct alignas(16) SS {
    float s[Nn];                          // 32KB
    unsigned long long top[Kk][RR];       // 32KB
    unsigned hkey[HASHSZ];                // 16KB
    float    hval[HASHSZ];                // 16KB (cumulative delta)
    float    hbase[HASHSZ];               // 16KB (base W; NaN = unfilled)
    unsigned list[LISTCAP];               // 9.5KB (all created slots)
    unsigned long long cand[CAND];        // 1.5KB
    unsigned short bent[Kk][BCAP];        // 16KB per-spark-row buckets
    int      bcnt[Kk];
    unsigned char row2b[Nn];              // 8KB row -> bucket (255 = none)
    float spec[Kk][32];                   // 8KB upfront hebbian-base prefetch
    float specR[Kk];
    int   spp[Kk]; float sen[Kk]; int srnd[Kk];
    int   next_all[Kk];
    int   list_cnt;
};

__device__ __forceinline__ unsigned hash_h(unsigned key) {
    return (key * 2654435761u) & (HASHSZ - 1);
}
__device__ __forceinline__ int hfind(SS* sm, unsigned key) {
    unsigned h = hash_h(key);
    while (true) {
        unsigned k = sm->hkey[h];
        if (k == key) return (int)h;
        if (k == 0xFFFFFFFFu) return -1;
        h = (h + 1) & (HASHSZ - 1);
    }
}
__device__ __forceinline__ void cp_async4(void* smem_dst, const void* gptr) {
    unsigned a = (unsigned)__cvta_generic_to_shared(smem_dst);
    asm volatile("cp.async.ca.shared.global [%0], [%1], 4;" :: "r"(a), "l"(gptr) : "memory");
}

// add delta; on new slot: register in list, prefetch base, append to bucket
__device__ void hadd2(SS* sm, const float* __restrict__ W, int r, int c, float d) {
    unsigned key = ((unsigned)r << 13) | (unsigned)c;
    unsigned h = hash_h(key);
    while (true) {
        unsigned k = sm->hkey[h];
        if (k == key) { atomicAdd(&sm->hval[h], d); return; }
        if (k == 0xFFFFFFFFu) {
            unsigned old = atomicCAS(&sm->hkey[h], 0xFFFFFFFFu, key);
            if (old == 0xFFFFFFFFu) {
                atomicAdd(&sm->hval[h], d);
                int li = atomicAdd(&sm->list_cnt, 1);
                sm->list[li] = h;
                cp_async4(&sm->hbase[h], W + (size_t)r * Nn + c);   // fire & forget
                unsigned b = sm->row2b[r];
                if (b != 255u) {
                    int p = atomicAdd(&sm->bcnt[b], 1);
                    if (p < BCAP) sm->bent[b][p] = (unsigned short)h;
                }
                return;
            }
            if (old == key) { atomicAdd(&sm->hval[h], d); return; }
        }
        h = (h + 1) & (HASHSZ - 1);
    }
}

// ---------------------------------------------------------------------------
// Kernel 2: sequential spark scan. Loop runs entirely in warp 0 (no CTA
// barriers inside); 256 threads used for init + epilogue.
// ---------------------------------------------------------------------------
__global__ void __launch_bounds__(256, 1) scan_kernel(
    const float* __restrict__ W,
    const float* __restrict__ energy,
    const int*   __restrict__ spark_pos,
    const int*   __restrict__ spark_age,
    const int*   __restrict__ randint_vals,
    const int*   __restrict__ step_ptr,
    float*       __restrict__ out)
{
    extern __shared__ unsigned char smraw[];
    SS* sm = reinterpret_cast<SS*>(smraw);
    const int tid  = threadIdx.x;
    const int lane = tid & 31;
    const int wid  = tid >> 5;

    const int step = step_ptr ? *step_ptr : 1;
    const int mode = ((step % 3) + 3) % 3;
    const float NANF = __int_as_float(0x7fffffff);

    // ---- init ----
    if (tid < Kk) {
        sm->spp[tid]  = spark_pos[tid];
        sm->sen[tid]  = energy[tid];
        sm->srnd[tid] = randint_vals[tid];
        sm->bcnt[tid] = 0;
    }
    if (tid == 0) sm->list_cnt = 0;
    // upfront spec prefetch (warp 0 is issuer and only reader)
    if (wid == 0) {
        if (mode != 2) {
            for (int i = lane; i < Kk * 32; i += 32) {
                int it = i >> 5, l = i & 31;
                int col = key_idx(__ldg(&g_top[it][l]));
                cp_async4(&sm->spec[it][l],
                          W + (size_t)col * Nn + __ldg(&spark_pos[it]));
            }
        } else {
            for (int it = lane; it < Kk; it += 32)
                cp_async4(&sm->specR[it],
                          W + (size_t)__ldg(&randint_vals[it]) * Nn + __ldg(&spark_pos[it]));
        }
        asm volatile("cp.async.commit_group;" ::: "memory");
    }
    for (int i = tid; i < Nn; i += 256) sm->s[i] = g_s[i];
    for (int i = tid; i < Nn; i += 256) sm->row2b[i] = 255u;
    {
        unsigned long long* td = &sm->top[0][0];
        const unsigned long long* tsrc = &g_top[0][0];
        for (int i = tid; i < Kk * RR; i += 256) td[i] = tsrc[i];
    }
    for (int i = tid; i < HASHSZ; i += 256) {
        sm->hkey[i] = 0xFFFFFFFFu; sm->hval[i] = 0.f; sm->hbase[i] = NANF;
    }
    __syncthreads();
    if (tid < Kk) {
        sm->row2b[sm->spp[tid]] = (unsigned char)tid;   // consistent per row
        if (spark_age[tid] < 5) {                        // force young sparks
            int p = sm->spp[tid];
            if (p >= 0 && p < Nn) sm->s[p] = 1.0f;
        }
    }
    __syncthreads();

    // =============== serial loop: warp 0 only ===============
    if (wid == 0) {
        asm volatile("cp.async.wait_group 0;" ::: "memory");   // spec ready

        for (int it = 0; it < Kk; ++it) {
            const int prev = sm->spp[it];
            const int bkt  = sm->row2b[prev];
            int nb = sm->bcnt[bkt]; if (nb > BCAP) nb = BCAP;

            // fresh values for this row's touched cols
            for (int j = lane; j < nb; j += 32) {
                int slot = sm->bent[bkt][j];
                unsigned key = sm->hkey[slot];
                int c = (int)(key & (Nn - 1));
                float b = sm->hbase[slot];
                if (b != b) { b = __ldg(&W[(size_t)prev * Nn + c]); sm->hbase[slot] = b; }
                sm->cand[RR + j] = pack64(valkey(b + sm->hval[slot]), c);
            }
            __syncwarp();

            unsigned long long mine[4];
            mine[0] = sm->top[it][lane];
            mine[1] = sm->top[it][lane + 32];
            mine[2] = (lane < nb)      ? sm->cand[RR + lane]      : 0ull;
            mine[3] = (lane + 32 < nb) ? sm->cand[RR + lane + 32] : 0ull;
            const bool ext = nb > 64;

            // zero stale base copies of touched cols
            for (int j = 0; j < nb; ++j) {
                int col = key_idx(sm->cand[RR + j]);      // broadcast LDS
                if (key_idx(mine[0]) == col) mine[0] = 0ull;
                if (key_idx(mine[1]) == col) mine[1] = 0ull;
            }

            // top-6 extraction
            const int nc = RR + nb;
            unsigned long long t[6];
            #pragma unroll
            for (int pp = 0; pp < 6; ++pp) {
                unsigned long long b = mine[0];
                if (mine[1] > b) b = mine[1];
                if (mine[2] > b) b = mine[2];
                if (mine[3] > b) b = mine[3];
                if (ext)
                    for (int j = RR + 64 + lane; j < nc; j += 32) {
                        unsigned long long v = sm->cand[j];
                        if (v > b) b = v;
                    }
                unsigned hi = (unsigned)(b >> 32);
                unsigned himax = __reduce_max_sync(0xFFFFFFFFu, hi);
                unsigned lo = (hi == himax) ? (unsigned)b : 0u;
                unsigned lomax = __reduce_max_sync(0xFFFFFFFFu, lo);
                unsigned long long win = ((unsigned long long)himax << 32) | lomax;
                t[pp] = win;
                #pragma unroll
                for (int q = 0; q < 4; ++q) if (mine[q] == win) mine[q] = 0ull;
                if (ext)
                    for (int j = RR + 64 + lane; j < nc; j += 32)
                        if (sm->cand[j] == win) sm->cand[j] = 0ull;
            }

            const int next = (mode == 2) ? sm->srnd[it] : key_idx(t[0]);

            int myc = (mode != 2) ? key_idx(sm->top[it][lane]) : -1;
            unsigned mmask = __ballot_sync(0xFFFFFFFFu, myc == next);

            float hnew = 0.f;
            if (lane == 0) {
                unsigned key = ((unsigned)next << 13) | (unsigned)prev;
                int slot = hfind(sm, key);
                float base; bool have = false;
                if (slot >= 0) {
                    float b = sm->hbase[slot];
                    if (b == b) { base = b; have = true; }
                }
                if (!have) {
                    if (mode == 2)       base = sm->specR[it];
                    else if (mmask)      base = sm->spec[it][__ffs(mmask) - 1];
                    else                 base = __ldg(&W[(size_t)next * Nn + prev]);
                }
                float cur = base + ((slot >= 0) ? sm->hval[slot] : 0.f);
                float sp  = sm->s[prev];
                hnew = cur * 0.95f + sp * 0.05f;
                if (slot >= 0) {
                    sm->hbase[slot] = base;
                    sm->hval[slot] += hnew - cur;
                } else {
                    unsigned h = hash_h(key);
                    while (sm->hkey[h] != 0xFFFFFFFFu) h = (h + 1) & (HASHSZ - 1);
                    sm->hkey[h]  = key;
                    sm->hbase[h] = base;
                    sm->hval[h]  = hnew - base;
                    int li = sm->list_cnt; sm->list[li] = h; sm->list_cnt = li + 1;
                    unsigned bb = sm->row2b[next];
                    if (bb != 255u) {
                        int p = sm->bcnt[bb];
                        if (p < BCAP) sm->bent[bb][p] = (unsigned short)h;
                        sm->bcnt[bb] = p + 1;
                    }
                }
                sm->s[next] = sm->sen[it] * 0.98f;
                sm->next_all[it] = next;
            }
            hnew = __shfl_sync(0xFFFFFFFFu, hnew, 0);   // sync + broadcast

            // top-5 after Hebbian: only in-row element (prev,prev) can change
            unsigned long long top5[5];
            if (next == prev) {
                unsigned long long cnd[7];
                int cn = 0;
                #pragma unroll
                for (int q = 0; q < 6; ++q)
                    if (key_idx(t[q]) != prev) cnd[cn++] = t[q];
                cnd[cn++] = pack64(valkey(hnew), prev);
                for (int a = 1; a < cn; ++a) {
                    unsigned long long kx = cnd[a];
                    int b = a - 1;
                    while (b >= 0 && cnd[b] < kx) { cnd[b + 1] = cnd[b]; --b; }
                    cnd[b + 1] = kx;
                }
                #pragma unroll
                for (int q = 0; q < 5; ++q) top5[q] = cnd[q];
            } else {
                #pragma unroll
                for (int q = 0; q < 5; ++q) top5[q] = t[q];
            }

            // ripple: 35 additive updates across lanes
            for (int u = lane; u < 35; u += 32) {
                int r, c; float d;
                if (u < 5)       { r = prev;                c = key_idx(top5[u]);   d = 0.01f;  }
                else if (u < 10) { r = key_idx(top5[u-5]);  c = prev;               d = 0.005f; }
                else {
                    int a = (u - 10) / 5, b2 = (u - 10) % 5;
                    r = key_idx(top5[a]); c = key_idx(top5[b2]); d = 0.003f;
                }
                hadd2(sm, W, r, c, d);
            }
            __syncwarp();
        }

        // make all in-flight hbase prefetches visible before epilogue
        asm volatile("cp.async.commit_group;" ::: "memory");
        asm volatile("cp.async.wait_group 0;" ::: "memory");
    }
    __syncthreads();

    // ------------------- epilogue (all 256 threads) -------------------
    const size_t oS = Kk;
    const size_t oW = (size_t)Kk + Nn;
    const size_t oE = oW + (size_t)Nn * Nn;
    const size_t oA = oE + Kk;

    if (tid < Kk) {
        float ed   = sm->sen[tid] * 0.98f;
        bool reset = ed < 0.05f;
        int pn = reset ? (tid % Nn) : sm->next_all[tid];
        out[tid]      = (float)pn;
        out[oE + tid] = reset ? 1.0f : ed;
        out[oA + tid] = (float)(reset ? 0 : (spark_age[tid] + 1));
    }
    for (int j = tid; j < Nn; j += 256) out[oS + j] = sm->s[j];

    int nl = sm->list_cnt;
    for (int j = tid; j < nl; j += 256) {
        unsigned slot = sm->list[j];
        unsigned key  = sm->hkey[slot];
        int r = (int)(key >> 13), c = (int)(key & (Nn - 1));
        float b = sm->hbase[slot];
        if (b != b) b = __ldg(&W[(size_t)r * Nn + c]);
        float v = (b + sm->hval[slot]) * 0.999f;
        out[oW + (size_t)r * Nn + c] = fminf(fmaxf(v, -2.f), 2.f);
    }
}

// ---------------------------------------------------------------------------
// launch
// ---------------------------------------------------------------------------
extern "C" void kernel_launch(void* const* d_in, const int* in_sizes, int n_in,
                              void* d_out, int out_size)
{
    const float* W      = (const float*)d_in[0];
    const float* s      = (const float*)d_in[1];
    const float* noise  = (const float*)d_in[2];
    // d_in[3] = unif : unused (scalar gumbel shift doesn't change argmax)
    const float* energy = (const float*)d_in[4];
    const int* spark_pos = (const int*)d_in[5];
    const int* spark_age = (const int*)d_in[6];
    const int* randint   = (const int*)d_in[7];
    const int* step      = (n_in > 8) ? (const int*)d_in[8] : nullptr;
    float* out = (float*)d_out;

    (void)in_sizes; (void)out_size;

    prep_kernel<<<296, 1024>>>(W, s, noise, spark_pos, out + (Kk + Nn));

    cudaFuncSetAttribute(scan_kernel, cudaFuncAttributeMaxDynamicSharedMemorySize,
                         (int)sizeof(SS));
    scan_kernel<<<1, 256, sizeof(SS)>>>(W, energy, spark_pos, spark_age,
                                        randint, step, out);
}

// round 9
// speedup vs baseline: 2.0231x; 2.0231x over previous
#include <cuda_runtime.h>
#include <cstdint>
#include <cstddef>

#define Nn 8192
#define Kk 64
#define RR 64                  // base top-R per spark row (sorted desc)
#define HASHSZ 4096
#define LISTCAP 2432
#define BCAP 128               // per-spark-row bucket capacity
#define CAND (RR + BCAP)
#define NGEMV 256              // 256 CTAs * 32 warps = 8192 rows
#define GRIDSZ (1 + Kk + NGEMV)

// ---------------------------------------------------------------------------
// device globals (scratch; persists across replays -> counters reset at end)
// ---------------------------------------------------------------------------
__device__ unsigned long long g_top[Kk][RR];
__device__ float g_sspark[Kk];
__device__ int g_spark_done;
__device__ int g_gemv_done;

__device__ __forceinline__ unsigned valkey(float v) {
    return ((v > 0.f) ? __float_as_uint(v) : 0u) + 1u;
}
__device__ __forceinline__ unsigned long long pack64(unsigned key, int col) {
    return ((unsigned long long)key << 32) | (unsigned)(~(unsigned)col);
}
__device__ __forceinline__ int key_idx(unsigned long long k) {
    return (int)(~(unsigned)k);
}
__device__ __forceinline__ unsigned hash_h(unsigned key) {
    return (key * 2654435761u) & (HASHSZ - 1);
}
__device__ __forceinline__ void cp_async4(void* smem_dst, const void* gptr) {
    unsigned a = (unsigned)__cvta_generic_to_shared(smem_dst);
    asm volatile("cp.async.ca.shared.global [%0], [%1], 4;" :: "r"(a), "l"(gptr) : "memory");
}

// ---------------------------------------------------------------------------
// Scan shared memory (dynamic)
// ---------------------------------------------------------------------------
struct alignas(16) SS {
    unsigned long long top[Kk][RR];       // 32KB sorted base top lists
    unsigned hkey[HASHSZ];                // 16KB
    float    hval[HASHSZ];                // 16KB cumulative delta
    float    hbase[HASHSZ];               // 16KB base W (NaN = unfilled)
    unsigned list[LISTCAP];               // all created slots (epilogue)
    unsigned long long cand[CAND];
    unsigned short bent[Kk][BCAP];        // per-spark-row buckets
    int      bcnt[Kk];
    unsigned char row2b[Nn];              // row -> bucket (255 = none)
    float spec[Kk][32];                   // upfront hebbian-base prefetch
    float specR[Kk];
    float s_spark[Kk];                    // live s at spark rows only
    int   spp[Kk]; float sen[Kk]; int srnd[Kk];
    int   next_all[Kk];
    int   list_cnt;
};

__device__ __forceinline__ int hfind(SS* sm, unsigned key) {
    unsigned h = hash_h(key);
    while (true) {
        unsigned k = sm->hkey[h];
        if (k == key) return (int)h;
        if (k == 0xFFFFFFFFu) return -1;
        h = (h + 1) & (HASHSZ - 1);
    }
}
// add delta; on new slot: register in list, prefetch base, append to bucket
__device__ void hadd2(SS* sm, const float* __restrict__ W, int r, int c, float d) {
    unsigned key = ((unsigned)r << 13) | (unsigned)c;
    unsigned h = hash_h(key);
    while (true) {
        unsigned k = sm->hkey[h];
        if (k == key) { atomicAdd(&sm->hval[h], d); return; }
        if (k == 0xFFFFFFFFu) {
            unsigned old = atomicCAS(&sm->hkey[h], 0xFFFFFFFFu, key);
            if (old == 0xFFFFFFFFu) {
                atomicAdd(&sm->hval[h], d);
                int li = atomicAdd(&sm->list_cnt, 1);
                sm->list[li] = h;
                cp_async4(&sm->hbase[h], W + (size_t)r * Nn + c);   // fire & forget
                unsigned b = sm->row2b[r];
                if (b != 255u) {
                    int p = atomicAdd(&sm->bcnt[b], 1);
                    if (p < BCAP) sm->bent[b][p] = (unsigned short)h;
                }
                return;
            }
            if (old == key) { atomicAdd(&sm->hval[h], d); return; }
        }
        h = (h + 1) & (HASHSZ - 1);
    }
}

// ---------------------------------------------------------------------------
// ONE fused kernel:
//   CTA 0            : sequential spark scan (spins on spark/gemv counters)
//   CTA 1..Kk        : spark row top-64 (sorted) + sigmoid  -> g_top/g_sspark
//   CTA Kk+1..Kk+256 : warp-per-row GEMV + decay copy, writes out_s/out_W
// ---------------------------------------------------------------------------
__global__ void __launch_bounds__(1024, 1) fused_kernel(
    const float* __restrict__ W,
    const float* __restrict__ s_in,
    const float* __restrict__ noise,
    const float* __restrict__ energy,
    const int*   __restrict__ spark_pos,
    const int*   __restrict__ spark_age,
    const int*   __restrict__ randint_vals,
    const int*   __restrict__ step_ptr,
    float*       __restrict__ out)
{
    __shared__ unsigned long long wl[32][RR];
    __shared__ float red[32];

    const int tid  = threadIdx.x;
    const int lane = tid & 31;
    const int wid  = tid >> 5;
    const int bid  = blockIdx.x;

    const size_t oS = Kk;
    const size_t oW = (size_t)Kk + Nn;
    const size_t oE = oW + (size_t)Nn * Nn;
    const size_t oA = oE + Kk;

    // ======================= GEMV CTAs =======================
    if (bid > Kk) {
        const int row = (bid - (Kk + 1)) * 32 + wid;
        const float4* wrow  = reinterpret_cast<const float4*>(W + (size_t)row * Nn);
        float4*       worow = reinterpret_cast<float4*>(out + oW + (size_t)row * Nn);
        const float4* s4    = reinterpret_cast<const float4*>(s_in);
        float acc = 0.f;
        #pragma unroll 8
        for (int k = lane; k < Nn / 4; k += 32) {
            float4 w  = __ldcs(&wrow[k]);
            float4 sv = __ldg(&s4[k]);
            acc += w.x * (sv.x * 0.95f) + w.y * (sv.y * 0.95f)
                 + w.z * (sv.z * 0.95f) + w.w * (sv.w * 0.95f);
            float4 o;
            o.x = fminf(fmaxf(w.x * 0.999f, -2.f), 2.f);
            o.y = fminf(fmaxf(w.y * 0.999f, -2.f), 2.f);
            o.z = fminf(fmaxf(w.z * 0.999f, -2.f), 2.f);
            o.w = fminf(fmaxf(w.w * 0.999f, -2.f), 2.f);
            __stcs(&worow[k], o);
        }
        #pragma unroll
        for (int off = 16; off; off >>= 1)
            acc += __shfl_xor_sync(0xFFFFFFFFu, acc, off);
        if (lane == 0) {
            float z = acc + 0.05f * noise[row];
            out[oS + row] = 1.0f / (1.0f + expf(-z));
        }
        __syncthreads();
        if (tid == 0) { __threadfence(); atomicAdd(&g_gemv_done, 1); }
        return;
    }

    // ======================= spark CTAs =======================
    if (bid >= 1) {
        const int b   = bid - 1;
        const int row = spark_pos[b];
        const float4* r4 = reinterpret_cast<const float4*>(W + (size_t)row * Nn);
        // ---- sorted top-64 of the row ----
        {
            const int cbase = (wid << 8) + (lane << 3);
            float4 a = __ldg(&r4[cbase >> 2]);
            float4 c = __ldg(&r4[(cbase >> 2) + 1]);
            unsigned k0 = valkey(a.x), k1 = valkey(a.y), k2 = valkey(a.z), k3 = valkey(a.w);
            unsigned k4 = valkey(c.x), k5 = valkey(c.y), k6 = valkey(c.z), k7 = valkey(c.w);
            for (int p = 0; p < RR; ++p) {
                unsigned bk = k0; int bj = 0;
                if (k1 > bk) { bk = k1; bj = 1; }
                if (k2 > bk) { bk = k2; bj = 2; }
                if (k3 > bk) { bk = k3; bj = 3; }
                if (k4 > bk) { bk = k4; bj = 4; }
                if (k5 > bk) { bk = k5; bj = 5; }
                if (k6 > bk) { bk = k6; bj = 6; }
                if (k7 > bk) { bk = k7; bj = 7; }
                unsigned kmax = __reduce_max_sync(0xFFFFFFFFu, bk);
                unsigned cnd = (bk == kmax) ? (unsigned)(cbase + bj) : 0xFFFFFFFFu;
                unsigned cmin = __reduce_min_sync(0xFFFFFFFFu, cnd);
                if (lane == 0) wl[wid][p] = pack64(kmax, (int)cmin);
                int rel = (int)cmin - cbase;
                if (rel >= 0 && rel < 8) {
                    if (rel == 0) k0 = 0; if (rel == 1) k1 = 0;
                    if (rel == 2) k2 = 0; if (rel == 3) k3 = 0;
                    if (rel == 4) k4 = 0; if (rel == 5) k5 = 0;
                    if (rel == 6) k6 = 0; if (rel == 7) k7 = 0;
                }
            }
            __syncthreads();
            if (wid == 0) {
                int head = 0;
                for (int p = 0; p < RR; ++p) {
                    unsigned long long cur = (head < RR) ? wl[lane][head] : 0ull;
                    unsigned hi = (unsigned)(cur >> 32);
                    unsigned kmax = __reduce_max_sync(0xFFFFFFFFu, hi);
                    unsigned lo = (hi == kmax) ? (unsigned)cur : 0u;
                    unsigned lomax = __reduce_max_sync(0xFFFFFFFFu, lo);
                    if (hi == kmax && (unsigned)cur == lomax) head++;
                    if (lane == 0)
                        g_top[b][p] = ((unsigned long long)kmax << 32) | lomax;
                }
            }
        }
        // ---- sigmoid of this row ----
        {
            const float4* s4 = reinterpret_cast<const float4*>(s_in);
            float4 w1 = __ldg(&r4[2 * tid]),     w2 = __ldg(&r4[2 * tid + 1]);
            float4 v1 = __ldg(&s4[2 * tid]),     v2 = __ldg(&s4[2 * tid + 1]);
            float acc = w1.x * (v1.x * 0.95f) + w1.y * (v1.y * 0.95f)
                      + w1.z * (v1.z * 0.95f) + w1.w * (v1.w * 0.95f)
                      + w2.x * (v2.x * 0.95f) + w2.y * (v2.y * 0.95f)
                      + w2.z * (v2.z * 0.95f) + w2.w * (v2.w * 0.95f);
            #pragma unroll
            for (int off = 16; off; off >>= 1)
                acc += __shfl_xor_sync(0xFFFFFFFFu, acc, off);
            if (lane == 0) red[wid] = acc;
            __syncthreads();
            if (wid == 0) {
                float v = red[lane];
                #pragma unroll
                for (int off = 16; off; off >>= 1)
                    v += __shfl_xor_sync(0xFFFFFFFFu, v, off);
                if (lane == 0) {
                    float z = v + 0.05f * noise[row];
                    g_sspark[b] = 1.0f / (1.0f + expf(-z));
                    __threadfence();
                    atomicAdd(&g_spark_done, 1);
                }
            }
        }
        return;
    }

    // ======================= scan CTA (bid == 0) =======================
    extern __shared__ unsigned char smraw[];
    SS* sm = reinterpret_cast<SS*>(smraw);

    const int step = step_ptr ? *step_ptr : 1;
    const int mode = ((step % 3) + 3) % 3;
    const float NANF = __int_as_float(0x7fffffff);

    if (tid < Kk) {
        sm->spp[tid]  = spark_pos[tid];
        sm->sen[tid]  = energy[tid];
        sm->srnd[tid] = randint_vals[tid];
        sm->bcnt[tid] = 0;
    }
    if (tid == 0) sm->list_cnt = 0;
    for (int i = tid; i < Nn; i += 1024) sm->row2b[i] = 255u;
    for (int i = tid; i < HASHSZ; i += 1024) {
        sm->hkey[i] = 0xFFFFFFFFu; sm->hval[i] = 0.f; sm->hbase[i] = NANF;
    }
    __syncthreads();
    if (tid < Kk) sm->row2b[sm->spp[tid]] = (unsigned char)tid;
    // wait for spark CTAs (top lists + sigmoids)
    if (tid == 0) {
        while (atomicAdd(&g_spark_done, 0) < Kk) __nanosleep(128);
    }
    __syncthreads();
    {
        unsigned long long* td = &sm->top[0][0];
        const unsigned long long* tsrc = &g_top[0][0];
        for (int i = tid; i < Kk * RR; i += 1024) td[i] = tsrc[i];
    }
    if (tid < Kk) sm->s_spark[tid] = g_sspark[tid];
    __syncthreads();
    if (tid < Kk && spark_age[tid] < 5) {          // force young sparks
        int p = sm->spp[tid];
        if (p >= 0 && p < Nn) sm->s_spark[sm->row2b[p]] = 1.0f;
    }
    __syncthreads();

    if (wid == 0) {
        // upfront hebbian-base speculative prefetch
        if (mode != 2) {
            for (int it = 0; it < Kk; ++it) {
                int col = key_idx(sm->top[it][lane]);
                cp_async4(&sm->spec[it][lane], W + (size_t)col * Nn + sm->spp[it]);
            }
        } else {
            for (int it = lane; it < Kk; it += 32)
                cp_async4(&sm->specR[it], W + (size_t)sm->srnd[it] * Nn + sm->spp[it]);
        }
        asm volatile("cp.async.commit_group;" ::: "memory");
        asm volatile("cp.async.wait_group 0;" ::: "memory");

        // =============== serial loop (warp 0 only) ===============
        for (int it = 0; it < Kk; ++it) {
            const int prev = sm->spp[it];
            const int bkt  = sm->row2b[prev];
            int nb = sm->bcnt[bkt]; if (nb > BCAP) nb = BCAP;

            unsigned long long t[6];
            if (nb == 0) {
                // FAST PATH: base list sorted -> top-6 is just the head
                #pragma unroll
                for (int q = 0; q < 6; ++q) t[q] = sm->top[it][q];
            } else {
                // slow path: merge touched entries
                for (int j = lane; j < nb; j += 32) {
                    int slot = sm->bent[bkt][j];
                    unsigned key = sm->hkey[slot];
                    int c = (int)(key & (Nn - 1));
                    float b = sm->hbase[slot];
                    if (b != b) { b = __ldg(&W[(size_t)prev * Nn + c]); sm->hbase[slot] = b; }
                    sm->cand[RR + j] = pack64(valkey(b + sm->hval[slot]), c);
                }
                __syncwarp();
                unsigned long long mine[4];
                mine[0] = sm->top[it][lane];
                mine[1] = sm->top[it][lane + 32];
                mine[2] = (lane < nb)      ? sm->cand[RR + lane]      : 0ull;
                mine[3] = (lane + 32 < nb) ? sm->cand[RR + lane + 32] : 0ull;
                const bool ext = nb > 64;
                for (int j = 0; j < nb; ++j) {
                    int col = key_idx(sm->cand[RR + j]);
                    if (key_idx(mine[0]) == col) mine[0] = 0ull;
                    if (key_idx(mine[1]) == col) mine[1] = 0ull;
                }
                const int nc = RR + nb;
                #pragma unroll
                for (int pp = 0; pp < 6; ++pp) {
                    unsigned long long b = mine[0];
                    if (mine[1] > b) b = mine[1];
                    if (mine[2] > b) b = mine[2];
                    if (mine[3] > b) b = mine[3];
                    if (ext)
                        for (int j = RR + 64 + lane; j < nc; j += 32) {
                            unsigned long long v = sm->cand[j];
                            if (v > b) b = v;
                        }
                    unsigned hi = (unsigned)(b >> 32);
                    unsigned himax = __reduce_max_sync(0xFFFFFFFFu, hi);
                    unsigned lo = (hi == himax) ? (unsigned)b : 0u;
                    unsigned lomax = __reduce_max_sync(0xFFFFFFFFu, lo);
                    unsigned long long win = ((unsigned long long)himax << 32) | lomax;
                    t[pp] = win;
                    #pragma unroll
                    for (int q = 0; q < 4; ++q) if (mine[q] == win) mine[q] = 0ull;
                    if (ext)
                        for (int j = RR + 64 + lane; j < nc; j += 32)
                            if (sm->cand[j] == win) sm->cand[j] = 0ull;
                }
            }

            const int next = (mode == 2) ? sm->srnd[it] : key_idx(t[0]);
            int myc = (mode != 2) ? key_idx(sm->top[it][lane]) : -1;
            unsigned mmask = __ballot_sync(0xFFFFFFFFu, myc == next);

            float hnew = 0.f;
            if (lane == 0) {
                unsigned key = ((unsigned)next << 13) | (unsigned)prev;
                int slot = hfind(sm, key);
                float base; bool have = false;
                if (slot >= 0) {
                    float b = sm->hbase[slot];
                    if (b == b) { base = b; have = true; }
                }
                if (!have) {
                    if (mode == 2)       base = sm->specR[it];
                    else if (mmask)      base = sm->spec[it][__ffs(mmask) - 1];
                    else                 base = __ldg(&W[(size_t)next * Nn + prev]);
                }
                float cur = base + ((slot >= 0) ? sm->hval[slot] : 0.f);
                float sp  = sm->s_spark[bkt];
                hnew = cur * 0.95f + sp * 0.05f;
                if (slot >= 0) {
                    sm->hbase[slot] = base;
                    sm->hval[slot] += hnew - cur;
                } else {
                    unsigned h = hash_h(key);
                    while (sm->hkey[h] != 0xFFFFFFFFu) h = (h + 1) & (HASHSZ - 1);
                    sm->hkey[h]  = key;
                    sm->hbase[h] = base;
                    sm->hval[h]  = hnew - base;
                    int li = sm->list_cnt; sm->list[li] = h; sm->list_cnt = li + 1;
                    unsigned bb = sm->row2b[next];
                    if (bb != 255u) {
                        int p = sm->bcnt[bb];
                        if (p < BCAP) sm->bent[bb][p] = (unsigned short)h;
                        sm->bcnt[bb] = p + 1;
                    }
                }
                unsigned bn = sm->row2b[next];
                if (bn != 255u) sm->s_spark[bn] = sm->sen[it] * 0.98f;
                sm->next_all[it] = next;
            }
            hnew = __shfl_sync(0xFFFFFFFFu, hnew, 0);

            // top-5 after Hebbian: only in-row element (prev,prev) can change
            unsigned long long top5[5];
            if (next == prev) {
                unsigned long long cnd[7];
                int cn = 0;
                #pragma unroll
                for (int q = 0; q < 6; ++q)
                    if (key_idx(t[q]) != prev) cnd[cn++] = t[q];
                cnd[cn++] = pack64(valkey(hnew), prev);
                for (int a = 1; a < cn; ++a) {
                    unsigned long long kx = cnd[a];
                    int b = a - 1;
                    while (b >= 0 && cnd[b] < kx) { cnd[b + 1] = cnd[b]; --b; }
                    cnd[b + 1] = kx;
                }
                #pragma unroll
                for (int q = 0; q < 5; ++q) top5[q] = cnd[q];
            } else {
                #pragma unroll
                for (int q = 0; q < 5; ++q) top5[q] = t[q];
            }

            // ripple: 35 additive updates across lanes
            for (int u = lane; u < 35; u += 32) {
                int r, c; float d;
                if (u < 5)       { r = prev;                c = key_idx(top5[u]);   d = 0.01f;  }
                else if (u < 10) { r = key_idx(top5[u-5]);  c = prev;               d = 0.005f; }
                else {
                    int a = (u - 10) / 5, b2 = (u - 10) % 5;
                    r = key_idx(top5[a]); c = key_idx(top5[b2]); d = 0.003f;
                }
                hadd2(sm, W, r, c, d);
            }
            __syncwarp();
        }
        asm volatile("cp.async.commit_group;" ::: "memory");
        asm volatile("cp.async.wait_group 0;" ::: "memory");
    }
    __syncthreads();

    // ---- epilogue part 1: pos/energy/age (scan-exclusive outputs) ----
    if (tid < Kk) {
        float ed   = sm->sen[tid] * 0.98f;
        bool reset = ed < 0.05f;
        int pn = reset ? (tid % Nn) : sm->next_all[tid];
        out[tid]      = (float)pn;
        out[oE + tid] = reset ? 1.0f : ed;
        out[oA + tid] = (float)(reset ? 0 : (spark_age[tid] + 1));
    }

    // ---- wait for GEMV CTAs, then apply s/W overwrites ----
    if (tid == 0) {
        while (atomicAdd(&g_gemv_done, 0) < NGEMV) __nanosleep(128);
    }
    __syncthreads();

    if (tid == 0) {
        // replay s writes in reference order (force, then sequential e_dec)
        for (int b = 0; b < Kk; ++b)
            if (spark_age[b] < 5) {
                int p = sm->spp[b];
                if (p >= 0 && p < Nn) out[oS + p] = 1.0f;
            }
        for (int it = 0; it < Kk; ++it)
            out[oS + sm->next_all[it]] = sm->sen[it] * 0.98f;
    }
    {
        int nl = sm->list_cnt;
        for (int j = tid; j < nl; j += 1024) {
            unsigned slot = sm->list[j];
            unsigned key  = sm->hkey[slot];
            int r = (int)(key >> 13), c = (int)(key & (Nn - 1));
            float b = sm->hbase[slot];
            if (b != b) b = __ldg(&W[(size_t)r * Nn + c]);
            float v = (b + sm->hval[slot]) * 0.999f;
            out[oW + (size_t)r * Nn + c] = fminf(fmaxf(v, -2.f), 2.f);
        }
    }
    __syncthreads();
    if (tid == 0) { g_spark_done = 0; g_gemv_done = 0; }   // replay determinism
}

// ---------------------------------------------------------------------------
// launch
// ---------------------------------------------------------------------------
extern "C" void kernel_launch(void* const* d_in, const int* in_sizes, int n_in,
                              void* d_out, int out_size)
{
    const float* W      = (const float*)d_in[0];
    const float* s      = (const float*)d_in[1];
    const float* noise  = (const float*)d_in[2];
    // d_in[3] = unif : unused (scalar gumbel shift doesn't change argmax)
    const float* energy = (const float*)d_in[4];
    const int* spark_pos = (const int*)d_in[5];
    const int* spark_age = (const int*)d_in[6];
    const int* randint   = (const int*)d_in[7];
    const int* step      = (n_in > 8) ? (const int*)d_in[8] : nullptr;
    float* out = (float*)d_out;

    (void)in_sizes; (void)out_size;

    cudaFuncSetAttribute(fused_kernel, cudaFuncAttributeMaxDynamicSharedMemorySize,
                         (int)sizeof(SS));
    fused_kernel<<<GRIDSZ, 1024, sizeof(SS)>>>(W, s, noise, energy, spark_pos,
                                               spark_age, randint, step, out);
}

// round 10
// speedup vs baseline: 2.0402x; 1.0084x over previous
#include <cuda_runtime.h>
#include <cstdint>
#include <cstddef>

#define Nn 8192
#define Kk 64
#define RR 64                  // base top-R per spark row (sorted desc)
#define HASHSZ 4096
#define LISTCAP 2432
#define BCAP 128               // per-spark-row bucket capacity
#define CAND (RR + BCAP)
#define NWORK 147              // worker CTAs (GEMV pool)
#define GRIDSZ (1 + NWORK)

// ---------------------------------------------------------------------------
// device globals (counters reset at end of each run for graph replay)
// ---------------------------------------------------------------------------
__device__ unsigned long long g_top[Kk][RR];
__device__ float g_sspark[Kk];
__device__ int g_spark_done;
__device__ int g_gemv_done;
__device__ int g_row_ctr;

__device__ __forceinline__ unsigned valkey(float v) {
    return ((v > 0.f) ? __float_as_uint(v) : 0u) + 1u;
}
__device__ __forceinline__ unsigned long long pack64(unsigned key, int col) {
    return ((unsigned long long)key << 32) | (unsigned)(~(unsigned)col);
}
__device__ __forceinline__ int key_idx(unsigned long long k) {
    return (int)(~(unsigned)k);
}
__device__ __forceinline__ unsigned hash_h(unsigned key) {
    return (key * 2654435761u) & (HASHSZ - 1);
}
__device__ __forceinline__ void cp_async4(void* smem_dst, const void* gptr) {
    unsigned a = (unsigned)__cvta_generic_to_shared(smem_dst);
    asm volatile("cp.async.ca.shared.global [%0], [%1], 4;" :: "r"(a), "l"(gptr) : "memory");
}

// ---------------------------------------------------------------------------
// Scan shared memory (dynamic)
// ---------------------------------------------------------------------------
struct alignas(16) SS {
    unsigned long long top[Kk][RR];       // 32KB sorted base top lists
    unsigned hkey[HASHSZ];                // 16KB
    float    hval[HASHSZ];                // 16KB cumulative delta
    float    hbase[HASHSZ];               // 16KB base W (NaN = unfilled)
    unsigned list[LISTCAP];               // all created slots (epilogue)
    unsigned long long cand[CAND];
    unsigned short bent[Kk][BCAP];        // per-spark-row buckets
    int      bcnt[Kk];
    unsigned char row2b[Nn];              // row -> bucket (255 = none)
    float spec[Kk][32];                   // upfront hebbian-base prefetch
    float specR[Kk];
    float s_spark[Kk];                    // live s at spark rows only
    int   spp[Kk]; float sen[Kk]; int srnd[Kk];
    int   next_all[Kk];
    int   list_cnt;
};

__device__ __forceinline__ int hfind(SS* sm, unsigned key) {
    unsigned h = hash_h(key);
    while (true) {
        unsigned k = sm->hkey[h];
        if (k == key) return (int)h;
        if (k == 0xFFFFFFFFu) return -1;
        h = (h + 1) & (HASHSZ - 1);
    }
}
// add delta; on new slot: register in list, prefetch base, append to bucket
__device__ void hadd2(SS* sm, const float* __restrict__ W, int r, int c, float d) {
    unsigned key = ((unsigned)r << 13) | (unsigned)c;
    unsigned h = hash_h(key);
    while (true) {
        unsigned k = sm->hkey[h];
        if (k == key) { atomicAdd(&sm->hval[h], d); return; }
        if (k == 0xFFFFFFFFu) {
            unsigned old = atomicCAS(&sm->hkey[h], 0xFFFFFFFFu, key);
            if (old == 0xFFFFFFFFu) {
                atomicAdd(&sm->hval[h], d);
                int li = atomicAdd(&sm->list_cnt, 1);
                sm->list[li] = h;
                cp_async4(&sm->hbase[h], W + (size_t)r * Nn + c);   // fire & forget
                unsigned b = sm->row2b[r];
                if (b != 255u) {
                    int p = atomicAdd(&sm->bcnt[b], 1);
                    if (p < BCAP) sm->bent[b][p] = (unsigned short)h;
                }
                return;
            }
            if (old == key) { atomicAdd(&sm->hval[h], d); return; }
        }
        h = (h + 1) & (HASHSZ - 1);
    }
}

// ---------------------------------------------------------------------------
// ONE fused kernel, one wave (148 CTAs):
//   CTA 0        : sequential spark scan (spins on spark/gemv counters)
//   CTA 1..64    : spark row top-64 + sigmoid, then join GEMV work queue
//   CTA 65..147  : GEMV work queue immediately
// GEMV rows are fetched warp-at-a-time from a global atomic counter.
// ---------------------------------------------------------------------------
__global__ void __launch_bounds__(1024, 1) fused_kernel(
    const float* __restrict__ W,
    const float* __restrict__ s_in,
    const float* __restrict__ noise,
    const float* __restrict__ energy,
    const int*   __restrict__ spark_pos,
    const int*   __restrict__ spark_age,
    const int*   __restrict__ randint_vals,
    const int*   __restrict__ step_ptr,
    float*       __restrict__ out)
{
    __shared__ unsigned long long wl[32][RR];
    __shared__ float red[32];

    const int tid  = threadIdx.x;
    const int lane = tid & 31;
    const int wid  = tid >> 5;
    const int bid  = blockIdx.x;

    const size_t oS = Kk;
    const size_t oW = (size_t)Kk + Nn;
    const size_t oE = oW + (size_t)Nn * Nn;
    const size_t oA = oE + Kk;

    // ======================= worker CTAs =======================
    if (bid >= 1) {
        // ---- spark prep (CTAs 1..Kk only) ----
        if (bid <= Kk) {
            const int b   = bid - 1;
            const int row = spark_pos[b];
            const float4* r4 = reinterpret_cast<const float4*>(W + (size_t)row * Nn);
            {
                const int cbase = (wid << 8) + (lane << 3);
                float4 a = __ldg(&r4[cbase >> 2]);
                float4 c = __ldg(&r4[(cbase >> 2) + 1]);
                unsigned k0 = valkey(a.x), k1 = valkey(a.y), k2 = valkey(a.z), k3 = valkey(a.w);
                unsigned k4 = valkey(c.x), k5 = valkey(c.y), k6 = valkey(c.z), k7 = valkey(c.w);
                for (int p = 0; p < RR; ++p) {
                    unsigned bk = k0; int bj = 0;
                    if (k1 > bk) { bk = k1; bj = 1; }
                    if (k2 > bk) { bk = k2; bj = 2; }
                    if (k3 > bk) { bk = k3; bj = 3; }
                    if (k4 > bk) { bk = k4; bj = 4; }
                    if (k5 > bk) { bk = k5; bj = 5; }
                    if (k6 > bk) { bk = k6; bj = 6; }
                    if (k7 > bk) { bk = k7; bj = 7; }
                    unsigned kmax = __reduce_max_sync(0xFFFFFFFFu, bk);
                    unsigned cnd = (bk == kmax) ? (unsigned)(cbase + bj) : 0xFFFFFFFFu;
                    unsigned cmin = __reduce_min_sync(0xFFFFFFFFu, cnd);
                    if (lane == 0) wl[wid][p] = pack64(kmax, (int)cmin);
                    int rel = (int)cmin - cbase;
                    if (rel >= 0 && rel < 8) {
                        if (rel == 0) k0 = 0; if (rel == 1) k1 = 0;
                        if (rel == 2) k2 = 0; if (rel == 3) k3 = 0;
                        if (rel == 4) k4 = 0; if (rel == 5) k5 = 0;
                        if (rel == 6) k6 = 0; if (rel == 7) k7 = 0;
                    }
                }
                __syncthreads();
                if (wid == 0) {
                    int head = 0;
                    for (int p = 0; p < RR; ++p) {
                        unsigned long long cur = (head < RR) ? wl[lane][head] : 0ull;
                        unsigned hi = (unsigned)(cur >> 32);
                        unsigned kmax = __reduce_max_sync(0xFFFFFFFFu, hi);
                        unsigned lo = (hi == kmax) ? (unsigned)cur : 0u;
                        unsigned lomax = __reduce_max_sync(0xFFFFFFFFu, lo);
                        if (hi == kmax && (unsigned)cur == lomax) head++;
                        if (lane == 0)
                            g_top[b][p] = ((unsigned long long)kmax << 32) | lomax;
                    }
                }
            }
            // sigmoid of this spark row (1024-thread reduce)
            {
                const float4* s4 = reinterpret_cast<const float4*>(s_in);
                float4 w1 = __ldg(&r4[2 * tid]),     w2 = __ldg(&r4[2 * tid + 1]);
                float4 v1 = __ldg(&s4[2 * tid]),     v2 = __ldg(&s4[2 * tid + 1]);
                float acc = w1.x * (v1.x * 0.95f) + w1.y * (v1.y * 0.95f)
                          + w1.z * (v1.z * 0.95f) + w1.w * (v1.w * 0.95f)
                          + w2.x * (v2.x * 0.95f) + w2.y * (v2.y * 0.95f)
                          + w2.z * (v2.z * 0.95f) + w2.w * (v2.w * 0.95f);
                #pragma unroll
                for (int off = 16; off; off >>= 1)
                    acc += __shfl_xor_sync(0xFFFFFFFFu, acc, off);
                if (lane == 0) red[wid] = acc;
                __syncthreads();
                if (wid == 0) {
                    float v = red[lane];
                    #pragma unroll
                    for (int off = 16; off; off >>= 1)
                        v += __shfl_xor_sync(0xFFFFFFFFu, v, off);
                    if (lane == 0) {
                        float z = v + 0.05f * noise[row];
                        g_sspark[b] = 1.0f / (1.0f + expf(-z));
                        __threadfence();
                        atomicAdd(&g_spark_done, 1);
                    }
                }
            }
        }

        // ---- GEMV work queue: warp grabs rows until exhausted ----
        const float4* s4 = reinterpret_cast<const float4*>(s_in);
        for (;;) {
            int row;
            if (lane == 0) row = atomicAdd(&g_row_ctr, 1);
            row = __shfl_sync(0xFFFFFFFFu, row, 0);
            if (row >= Nn) break;

            const float4* wrow  = reinterpret_cast<const float4*>(W + (size_t)row * Nn);
            float4*       worow = reinterpret_cast<float4*>(out + oW + (size_t)row * Nn);
            float acc = 0.f;
            #pragma unroll 8
            for (int k = lane; k < Nn / 4; k += 32) {
                float4 w  = __ldcs(&wrow[k]);
                float4 sv = __ldg(&s4[k]);
                acc += w.x * (sv.x * 0.95f) + w.y * (sv.y * 0.95f)
                     + w.z * (sv.z * 0.95f) + w.w * (sv.w * 0.95f);
                float4 o;
                o.x = fminf(fmaxf(w.x * 0.999f, -2.f), 2.f);
                o.y = fminf(fmaxf(w.y * 0.999f, -2.f), 2.f);
                o.z = fminf(fmaxf(w.z * 0.999f, -2.f), 2.f);
                o.w = fminf(fmaxf(w.w * 0.999f, -2.f), 2.f);
                __stcs(&worow[k], o);
            }
            #pragma unroll
            for (int off = 16; off; off >>= 1)
                acc += __shfl_xor_sync(0xFFFFFFFFu, acc, off);
            if (lane == 0) {
                float z = acc + 0.05f * noise[row];
                out[oS + row] = 1.0f / (1.0f + expf(-z));
            }
        }
        __syncthreads();
        if (tid == 0) { __threadfence(); atomicAdd(&g_gemv_done, 1); }
        return;
    }

    // ======================= scan CTA (bid == 0) =======================
    extern __shared__ unsigned char smraw[];
    SS* sm = reinterpret_cast<SS*>(smraw);

    const int step = step_ptr ? *step_ptr : 1;
    const int mode = ((step % 3) + 3) % 3;
    const float NANF = __int_as_float(0x7fffffff);

    if (tid < Kk) {
        sm->spp[tid]  = spark_pos[tid];
        sm->sen[tid]  = energy[tid];
        sm->srnd[tid] = randint_vals[tid];
        sm->bcnt[tid] = 0;
    }
    if (tid == 0) sm->list_cnt = 0;
    for (int i = tid; i < Nn; i += 1024) sm->row2b[i] = 255u;
    for (int i = tid; i < HASHSZ; i += 1024) {
        sm->hkey[i] = 0xFFFFFFFFu; sm->hval[i] = 0.f; sm->hbase[i] = NANF;
    }
    __syncthreads();
    if (tid < Kk) sm->row2b[sm->spp[tid]] = (unsigned char)tid;
    // wait for spark CTAs (top lists + sigmoids)
    if (tid == 0) {
        while (atomicAdd(&g_spark_done, 0) < Kk) __nanosleep(128);
    }
    __syncthreads();
    {
        unsigned long long* td = &sm->top[0][0];
        const unsigned long long* tsrc = &g_top[0][0];
        for (int i = tid; i < Kk * RR; i += 1024) td[i] = tsrc[i];
    }
    if (tid < Kk) sm->s_spark[tid] = g_sspark[tid];
    __syncthreads();
    if (tid < Kk && spark_age[tid] < 5) {          // force young sparks
        int p = sm->spp[tid];
        if (p >= 0 && p < Nn) sm->s_spark[sm->row2b[p]] = 1.0f;
    }
    __syncthreads();

    if (wid == 0) {
        // upfront hebbian-base speculative prefetch
        if (mode != 2) {
            for (int it = 0; it < Kk; ++it) {
                int col = key_idx(sm->top[it][lane]);
                cp_async4(&sm->spec[it][lane], W + (size_t)col * Nn + sm->spp[it]);
            }
        } else {
            for (int it = lane; it < Kk; it += 32)
                cp_async4(&sm->specR[it], W + (size_t)sm->srnd[it] * Nn + sm->spp[it]);
        }
        asm volatile("cp.async.commit_group;" ::: "memory");
        asm volatile("cp.async.wait_group 0;" ::: "memory");

        // =============== serial loop (warp 0 only) ===============
        for (int it = 0; it < Kk; ++it) {
            const int prev = sm->spp[it];
            const int bkt  = sm->row2b[prev];
            int nb = sm->bcnt[bkt]; if (nb > BCAP) nb = BCAP;

            unsigned long long t[6];
            if (nb == 0) {
                // FAST PATH: base list sorted -> top-6 is just the head
                #pragma unroll
                for (int q = 0; q < 6; ++q) t[q] = sm->top[it][q];
            } else {
                // slow path: merge touched entries
                for (int j = lane; j < nb; j += 32) {
                    int slot = sm->bent[bkt][j];
                    unsigned key = sm->hkey[slot];
                    int c = (int)(key & (Nn - 1));
                    float b = sm->hbase[slot];
                    if (b != b) { b = __ldg(&W[(size_t)prev * Nn + c]); sm->hbase[slot] = b; }
                    sm->cand[RR + j] = pack64(valkey(b + sm->hval[slot]), c);
                }
                __syncwarp();
                unsigned long long mine[4];
                mine[0] = sm->top[it][lane];
                mine[1] = sm->top[it][lane + 32];
                mine[2] = (lane < nb)      ? sm->cand[RR + lane]      : 0ull;
                mine[3] = (lane + 32 < nb) ? sm->cand[RR + lane + 32] : 0ull;
                const bool ext = nb > 64;
                for (int j = 0; j < nb; ++j) {
                    int col = key_idx(sm->cand[RR + j]);
                    if (key_idx(mine[0]) == col) mine[0] = 0ull;
                    if (key_idx(mine[1]) == col) mine[1] = 0ull;
                }
                const int nc = RR + nb;
                #pragma unroll
                for (int pp = 0; pp < 6; ++pp) {
                    unsigned long long b = mine[0];
                    if (mine[1] > b) b = mine[1];
                    if (mine[2] > b) b = mine[2];
                    if (mine[3] > b) b = mine[3];
                    if (ext)
                        for (int j = RR + 64 + lane; j < nc; j += 32) {
                            unsigned long long v = sm->cand[j];
                            if (v > b) b = v;
                        }
                    unsigned hi = (unsigned)(b >> 32);
                    unsigned himax = __reduce_max_sync(0xFFFFFFFFu, hi);
                    unsigned lo = (hi == himax) ? (unsigned)b : 0u;
                    unsigned lomax = __reduce_max_sync(0xFFFFFFFFu, lo);
                    unsigned long long win = ((unsigned long long)himax << 32) | lomax;
                    t[pp] = win;
                    #pragma unroll
                    for (int q = 0; q < 4; ++q) if (mine[q] == win) mine[q] = 0ull;
                    if (ext)
                        for (int j = RR + 64 + lane; j < nc; j += 32)
                            if (sm->cand[j] == win) sm->cand[j] = 0ull;
                }
            }

            const int next = (mode == 2) ? sm->srnd[it] : key_idx(t[0]);
            int myc = (mode != 2) ? key_idx(sm->top[it][lane]) : -1;
            unsigned mmask = __ballot_sync(0xFFFFFFFFu, myc == next);

            float hnew = 0.f;
            if (lane == 0) {
                unsigned key = ((unsigned)next << 13) | (unsigned)prev;
                int slot = hfind(sm, key);
                float base; bool have = false;
                if (slot >= 0) {
                    float b = sm->hbase[slot];
                    if (b == b) { base = b; have = true; }
                }
                if (!have) {
                    if (mode == 2)       base = sm->specR[it];
                    else if (mmask)      base = sm->spec[it][__ffs(mmask) - 1];
                    else                 base = __ldg(&W[(size_t)next * Nn + prev]);
                }
                float cur = base + ((slot >= 0) ? sm->hval[slot] : 0.f);
                float sp  = sm->s_spark[bkt];
                hnew = cur * 0.95f + sp * 0.05f;
                if (slot >= 0) {
                    sm->hbase[slot] = base;
                    sm->hval[slot] += hnew - cur;
                } else {
                    unsigned h = hash_h(key);
                    while (sm->hkey[h] != 0xFFFFFFFFu) h = (h + 1) & (HASHSZ - 1);
                    sm->hkey[h]  = key;
                    sm->hbase[h] = base;
                    sm->hval[h]  = hnew - base;
                    int li = sm->list_cnt; sm->list[li] = h; sm->list_cnt = li + 1;
                    unsigned bb = sm->row2b[next];
                    if (bb != 255u) {
                        int p = sm->bcnt[bb];
                        if (p < BCAP) sm->bent[bb][p] = (unsigned short)h;
                        sm->bcnt[bb] = p + 1;
                    }
                }
                unsigned bn = sm->row2b[next];
                if (bn != 255u) sm->s_spark[bn] = sm->sen[it] * 0.98f;
                sm->next_all[it] = next;
            }
            hnew = __shfl_sync(0xFFFFFFFFu, hnew, 0);

            // top-5 after Hebbian: only in-row element (prev,prev) can change
            unsigned long long top5[5];
            if (next == prev) {
                unsigned long long cnd[7];
                int cn = 0;
                #pragma unroll
                for (int q = 0; q < 6; ++q)
                    if (key_idx(t[q]) != prev) cnd[cn++] = t[q];
                cnd[cn++] = pack64(valkey(hnew), prev);
                for (int a = 1; a < cn; ++a) {
                    unsigned long long kx = cnd[a];
                    int b = a - 1;
                    while (b >= 0 && cnd[b] < kx) { cnd[b + 1] = cnd[b]; --b; }
                    cnd[b + 1] = kx;
                }
                #pragma unroll
                for (int q = 0; q < 5; ++q) top5[q] = cnd[q];
            } else {
                #pragma unroll
                for (int q = 0; q < 5; ++q) top5[q] = t[q];
            }

            // ripple: 35 additive updates across lanes
            for (int u = lane; u < 35; u += 32) {
                int r, c; float d;
                if (u < 5)       { r = prev;                c = key_idx(top5[u]);   d = 0.01f;  }
                else if (u < 10) { r = key_idx(top5[u-5]);  c = prev;               d = 0.005f; }
                else {
                    int a = (u - 10) / 5, b2 = (u - 10) % 5;
                    r = key_idx(top5[a]); c = key_idx(top5[b2]); d = 0.003f;
                }
                hadd2(sm, W, r, c, d);
            }
            __syncwarp();
        }
        asm volatile("cp.async.commit_group;" ::: "memory");
        asm volatile("cp.async.wait_group 0;" ::: "memory");
    }
    __syncthreads();

    // ---- epilogue part 1: pos/energy/age (scan-exclusive outputs) ----
    if (tid < Kk) {
        float ed   = sm->sen[tid] * 0.98f;
        bool reset = ed < 0.05f;
        int pn = reset ? (tid % Nn) : sm->next_all[tid];
        out[tid]      = (float)pn;
        out[oE + tid] = reset ? 1.0f : ed;
        out[oA + tid] = (float)(reset ? 0 : (spark_age[tid] + 1));
    }

    // ---- wait for GEMV workers, then apply s/W overwrites ----
    if (tid == 0) {
        while (atomicAdd(&g_gemv_done, 0) < NWORK) __nanosleep(128);
    }
    __syncthreads();

    if (tid == 0) {
        // replay s writes in reference order (force, then sequential e_dec)
        for (int b = 0; b < Kk; ++b)
            if (spark_age[b] < 5) {
                int p = sm->spp[b];
                if (p >= 0 && p < Nn) out[oS + p] = 1.0f;
            }
        for (int it = 0; it < Kk; ++it)
            out[oS + sm->next_all[it]] = sm->sen[it] * 0.98f;
    }
    {
        int nl = sm->list_cnt;
        for (int j = tid; j < nl; j += 1024) {
            unsigned slot = sm->list[j];
            unsigned key  = sm->hkey[slot];
            int r = (int)(key >> 13), c = (int)(key & (Nn - 1));
            float b = sm->hbase[slot];
            if (b != b) b = __ldg(&W[(size_t)r * Nn + c]);
            float v = (b + sm->hval[slot]) * 0.999f;
            out[oW + (size_t)r * Nn + c] = fminf(fmaxf(v, -2.f), 2.f);
        }
    }
    __syncthreads();
    if (tid == 0) {                       // replay determinism
        g_spark_done = 0; g_gemv_done = 0; g_row_ctr = 0;
    }
}

// ---------------------------------------------------------------------------
// launch
// ---------------------------------------------------------------------------
extern "C" void kernel_launch(void* const* d_in, const int* in_sizes, int n_in,
                              void* d_out, int out_size)
{
    const float* W      = (const float*)d_in[0];
    const float* s      = (const float*)d_in[1];
    const float* noise  = (const float*)d_in[2];
    // d_in[3] = unif : unused (scalar gumbel shift doesn't change argmax)
    const float* energy = (const float*)d_in[4];
    const int* spark_pos = (const int*)d_in[5];
    const int* spark_age = (const int*)d_in[6];
    const int* randint   = (const int*)d_in[7];
    const int* step      = (n_in > 8) ? (const int*)d_in[8] : nullptr;
    float* out = (float*)d_out;

    (void)in_sizes; (void)out_size;

    cudaFuncSetAttribute(fused_kernel, cudaFuncAttributeMaxDynamicSharedMemorySize,
                         (int)sizeof(SS));
    fused_kernel<<<GRIDSZ, 1024, sizeof(SS)>>>(W, s, noise, energy, spark_pos,
                                               spark_age, randint, step, out);
}

// round 11
// speedup vs baseline: 2.0404x; 1.0001x over previous
#include <cuda_runtime.h>
#include <cstdint>
#include <cstddef>

#define Nn 8192
#define Kk 64
#define RR 64                  // base top-R per spark row (sorted desc)
#define HASHSZ 4096
#define LISTCAP 2432
#define BCAP 128               // per-spark-row bucket capacity
#define CAND (RR + BCAP)
#define NWORK 147              // worker CTAs (GEMV pool)
#define GRIDSZ (1 + NWORK)

// ---------------------------------------------------------------------------
// device globals (counters reset at end of each run for graph replay)
// ---------------------------------------------------------------------------
__device__ unsigned long long g_top[Kk][RR];
__device__ float g_sspark[Kk];
__device__ int g_spark_done;
__device__ int g_gemv_done;
__device__ int g_row_ctr;

__device__ __forceinline__ unsigned valkey(float v) {
    return ((v > 0.f) ? __float_as_uint(v) : 0u) + 1u;
}
__device__ __forceinline__ unsigned long long pack64(unsigned key, int col) {
    return ((unsigned long long)key << 32) | (unsigned)(~(unsigned)col);
}
__device__ __forceinline__ int key_idx(unsigned long long k) {
    return (int)(~(unsigned)k);
}
__device__ __forceinline__ unsigned hash_h(unsigned key) {
    return (key * 2654435761u) & (HASHSZ - 1);
}
__device__ __forceinline__ void cp_async4(void* smem_dst, const void* gptr) {
    unsigned a = (unsigned)__cvta_generic_to_shared(smem_dst);
    asm volatile("cp.async.ca.shared.global [%0], [%1], 4;" :: "r"(a), "l"(gptr) : "memory");
}

// ---------------------------------------------------------------------------
// Scan shared memory (dynamic)
// ---------------------------------------------------------------------------
struct alignas(16) SS {
    unsigned long long top[Kk][RR];       // 32KB sorted base top lists
    unsigned hkey[HASHSZ];                // 16KB
    float    hval[HASHSZ];                // 16KB cumulative delta
    float    hbase[HASHSZ];               // 16KB base W (NaN = unfilled)
    unsigned list[LISTCAP];               // all created slots (epilogue)
    unsigned long long cand[CAND];
    unsigned short bent[Kk][BCAP];        // per-spark-row buckets
    int      bcnt[Kk];
    unsigned char row2b[Nn];              // row -> bucket (255 = none)
    float spec[Kk][32];                   // upfront hebbian-base prefetch
    float specR[Kk];
    float s_spark[Kk];                    // live s at spark rows only
    int   spp[Kk]; float sen[Kk]; int srnd[Kk];
    int   next_all[Kk];
    int   list_cnt;
};

__device__ __forceinline__ int hfind(SS* sm, unsigned key) {
    unsigned h = hash_h(key);
    while (true) {
        unsigned k = sm->hkey[h];
        if (k == key) return (int)h;
        if (k == 0xFFFFFFFFu) return -1;
        h = (h + 1) & (HASHSZ - 1);
    }
}
// add delta; on new slot: register in list + bucket. NO base prefetch here —
// bases are lazily fetched (slow path / epilogue). Keeps the serial loop free
// of cp.async issue backpressure.
__device__ void hadd(SS* sm, int r, int c, float d) {
    unsigned key = ((unsigned)r << 13) | (unsigned)c;
    unsigned h = hash_h(key);
    while (true) {
        unsigned k = sm->hkey[h];
        if (k == key) { atomicAdd(&sm->hval[h], d); return; }
        if (k == 0xFFFFFFFFu) {
            unsigned old = atomicCAS(&sm->hkey[h], 0xFFFFFFFFu, key);
            if (old == 0xFFFFFFFFu) {
                atomicAdd(&sm->hval[h], d);
                int li = atomicAdd(&sm->list_cnt, 1);
                sm->list[li] = h;
                unsigned b = sm->row2b[r];
                if (b != 255u) {
                    int p = atomicAdd(&sm->bcnt[b], 1);
                    if (p < BCAP) sm->bent[b][p] = (unsigned short)h;
                }
                return;
            }
            if (old == key) { atomicAdd(&sm->hval[h], d); return; }
        }
        h = (h + 1) & (HASHSZ - 1);
    }
}

// ---------------------------------------------------------------------------
// ONE fused kernel, one wave (148 CTAs):
//   CTA 0        : sequential spark scan (spins on spark/gemv counters)
//   CTA 1..64    : spark row top-64 + sigmoid, then join GEMV work queue
//   CTA 65..147  : GEMV work queue immediately
// ---------------------------------------------------------------------------
__global__ void __launch_bounds__(1024, 1) fused_kernel(
    const float* __restrict__ W,
    const float* __restrict__ s_in,
    const float* __restrict__ noise,
    const float* __restrict__ energy,
    const int*   __restrict__ spark_pos,
    const int*   __restrict__ spark_age,
    const int*   __restrict__ randint_vals,
    const int*   __restrict__ step_ptr,
    float*       __restrict__ out)
{
    __shared__ unsigned long long wl[32][RR];
    __shared__ float red[32];

    const int tid  = threadIdx.x;
    const int lane = tid & 31;
    const int wid  = tid >> 5;
    const int bid  = blockIdx.x;

    const size_t oS = Kk;
    const size_t oW = (size_t)Kk + Nn;
    const size_t oE = oW + (size_t)Nn * Nn;
    const size_t oA = oE + Kk;

    // ======================= worker CTAs =======================
    if (bid >= 1) {
        // ---- spark prep (CTAs 1..Kk only) ----
        if (bid <= Kk) {
            const int b   = bid - 1;
            const int row = spark_pos[b];
            const float4* r4 = reinterpret_cast<const float4*>(W + (size_t)row * Nn);
            {
                const int cbase = (wid << 8) + (lane << 3);
                float4 a = __ldg(&r4[cbase >> 2]);
                float4 c = __ldg(&r4[(cbase >> 2) + 1]);
                unsigned k0 = valkey(a.x), k1 = valkey(a.y), k2 = valkey(a.z), k3 = valkey(a.w);
                unsigned k4 = valkey(c.x), k5 = valkey(c.y), k6 = valkey(c.z), k7 = valkey(c.w);
                for (int p = 0; p < RR; ++p) {
                    unsigned bk = k0; int bj = 0;
                    if (k1 > bk) { bk = k1; bj = 1; }
                    if (k2 > bk) { bk = k2; bj = 2; }
                    if (k3 > bk) { bk = k3; bj = 3; }
                    if (k4 > bk) { bk = k4; bj = 4; }
                    if (k5 > bk) { bk = k5; bj = 5; }
                    if (k6 > bk) { bk = k6; bj = 6; }
                    if (k7 > bk) { bk = k7; bj = 7; }
                    unsigned kmax = __reduce_max_sync(0xFFFFFFFFu, bk);
                    unsigned cnd = (bk == kmax) ? (unsigned)(cbase + bj) : 0xFFFFFFFFu;
                    unsigned cmin = __reduce_min_sync(0xFFFFFFFFu, cnd);
                    if (lane == 0) wl[wid][p] = pack64(kmax, (int)cmin);
                    int rel = (int)cmin - cbase;
                    if (rel >= 0 && rel < 8) {
                        if (rel == 0) k0 = 0; if (rel == 1) k1 = 0;
                        if (rel == 2) k2 = 0; if (rel == 3) k3 = 0;
                        if (rel == 4) k4 = 0; if (rel == 5) k5 = 0;
                        if (rel == 6) k6 = 0; if (rel == 7) k7 = 0;
                    }
                }
                __syncthreads();
                if (wid == 0) {
                    int head = 0;
                    for (int p = 0; p < RR; ++p) {
                        unsigned long long cur = (head < RR) ? wl[lane][head] : 0ull;
                        unsigned hi = (unsigned)(cur >> 32);
                        unsigned kmax = __reduce_max_sync(0xFFFFFFFFu, hi);
                        unsigned lo = (hi == kmax) ? (unsigned)cur : 0u;
                        unsigned lomax = __reduce_max_sync(0xFFFFFFFFu, lo);
                        if (hi == kmax && (unsigned)cur == lomax) head++;
                        if (lane == 0)
                            g_top[b][p] = ((unsigned long long)kmax << 32) | lomax;
                    }
                }
            }
            // sigmoid of this spark row (1024-thread reduce)
            {
                const float4* s4 = reinterpret_cast<const float4*>(s_in);
                float4 w1 = __ldg(&r4[2 * tid]),     w2 = __ldg(&r4[2 * tid + 1]);
                float4 v1 = __ldg(&s4[2 * tid]),     v2 = __ldg(&s4[2 * tid + 1]);
                float acc = w1.x * (v1.x * 0.95f) + w1.y * (v1.y * 0.95f)
                          + w1.z * (v1.z * 0.95f) + w1.w * (v1.w * 0.95f)
                          + w2.x * (v2.x * 0.95f) + w2.y * (v2.y * 0.95f)
                          + w2.z * (v2.z * 0.95f) + w2.w * (v2.w * 0.95f);
                #pragma unroll
                for (int off = 16; off; off >>= 1)
                    acc += __shfl_xor_sync(0xFFFFFFFFu, acc, off);
                if (lane == 0) red[wid] = acc;
                __syncthreads();
                if (wid == 0) {
                    float v = red[lane];
                    #pragma unroll
                    for (int off = 16; off; off >>= 1)
                        v += __shfl_xor_sync(0xFFFFFFFFu, v, off);
                    if (lane == 0) {
                        float z = v + 0.05f * noise[row];
                        g_sspark[b] = 1.0f / (1.0f + expf(-z));
                        __threadfence();
                        atomicAdd(&g_spark_done, 1);
                    }
                }
            }
        }

        // ---- GEMV work queue: warp grabs rows until exhausted ----
        const float4* s4 = reinterpret_cast<const float4*>(s_in);
        for (;;) {
            int row;
            if (lane == 0) row = atomicAdd(&g_row_ctr, 1);
            row = __shfl_sync(0xFFFFFFFFu, row, 0);
            if (row >= Nn) break;

            const float4* wrow  = reinterpret_cast<const float4*>(W + (size_t)row * Nn);
            float4*       worow = reinterpret_cast<float4*>(out + oW + (size_t)row * Nn);
            float acc = 0.f;
            #pragma unroll 8
            for (int k = lane; k < Nn / 4; k += 32) {
                float4 w  = __ldcs(&wrow[k]);
                float4 sv = __ldg(&s4[k]);
                acc += w.x * (sv.x * 0.95f) + w.y * (sv.y * 0.95f)
                     + w.z * (sv.z * 0.95f) + w.w * (sv.w * 0.95f);
                float4 o;
                o.x = fminf(fmaxf(w.x * 0.999f, -2.f), 2.f);
                o.y = fminf(fmaxf(w.y * 0.999f, -2.f), 2.f);
                o.z = fminf(fmaxf(w.z * 0.999f, -2.f), 2.f);
                o.w = fminf(fmaxf(w.w * 0.999f, -2.f), 2.f);
                __stcs(&worow[k], o);
            }
            #pragma unroll
            for (int off = 16; off; off >>= 1)
                acc += __shfl_xor_sync(0xFFFFFFFFu, acc, off);
            if (lane == 0) {
                float z = acc + 0.05f * noise[row];
                out[oS + row] = 1.0f / (1.0f + expf(-z));
            }
        }
        __syncthreads();
        if (tid == 0) { __threadfence(); atomicAdd(&g_gemv_done, 1); }
        return;
    }

    // ======================= scan CTA (bid == 0) =======================
    extern __shared__ unsigned char smraw[];
    SS* sm = reinterpret_cast<SS*>(smraw);

    const int step = step_ptr ? *step_ptr : 1;
    const int mode = ((step % 3) + 3) % 3;
    const float NANF = __int_as_float(0x7fffffff);

    if (tid < Kk) {
        sm->spp[tid]  = spark_pos[tid];
        sm->sen[tid]  = energy[tid];
        sm->srnd[tid] = randint_vals[tid];
        sm->bcnt[tid] = 0;
    }
    if (tid == 0) sm->list_cnt = 0;
    for (int i = tid; i < Nn; i += 1024) sm->row2b[i] = 255u;
    for (int i = tid; i < HASHSZ; i += 1024) {
        sm->hkey[i] = 0xFFFFFFFFu; sm->hval[i] = 0.f; sm->hbase[i] = NANF;
    }
    __syncthreads();
    if (tid < Kk) sm->row2b[sm->spp[tid]] = (unsigned char)tid;
    // wait for spark CTAs (top lists + sigmoids)
    if (tid == 0) {
        while (atomicAdd(&g_spark_done, 0) < Kk) __nanosleep(128);
    }
    __syncthreads();
    {
        unsigned long long* td = &sm->top[0][0];
        const unsigned long long* tsrc = &g_top[0][0];
        for (int i = tid; i < Kk * RR; i += 1024) td[i] = tsrc[i];
    }
    if (tid < Kk) sm->s_spark[tid] = g_sspark[tid];
    __syncthreads();
    if (tid < Kk && spark_age[tid] < 5) {          // force young sparks
        int p = sm->spp[tid];
        if (p >= 0 && p < Nn) sm->s_spark[sm->row2b[p]] = 1.0f;
    }
    __syncthreads();

    if (wid == 0) {
        // upfront hebbian-base speculative prefetch
        if (mode != 2) {
            for (int it = 0; it < Kk; ++it) {
                int col = key_idx(sm->top[it][lane]);
                cp_async4(&sm->spec[it][lane], W + (size_t)col * Nn + sm->spp[it]);
            }
        } else {
            for (int it = lane; it < Kk; it += 32)
                cp_async4(&sm->specR[it], W + (size_t)sm->srnd[it] * Nn + sm->spp[it]);
        }
        asm volatile("cp.async.commit_group;" ::: "memory");
        asm volatile("cp.async.wait_group 0;" ::: "memory");

        // =============== serial loop (warp 0 only) ===============
        for (int it = 0; it < Kk; ++it) {
            const int prev = sm->spp[it];
            const int bkt  = sm->row2b[prev];
            int nb = sm->bcnt[bkt]; if (nb > BCAP) nb = BCAP;

            unsigned long long t[6];
            if (nb == 0) {
                // FAST PATH: base list sorted -> top-6 is just the head
                #pragma unroll
                for (int q = 0; q < 6; ++q) t[q] = sm->top[it][q];
            } else {
                // slow path: merge touched entries
                for (int j = lane; j < nb; j += 32) {
                    int slot = sm->bent[bkt][j];
                    unsigned key = sm->hkey[slot];
                    int c = (int)(key & (Nn - 1));
                    float b = sm->hbase[slot];
                    if (b != b) { b = __ldg(&W[(size_t)prev * Nn + c]); sm->hbase[slot] = b; }
                    sm->cand[RR + j] = pack64(valkey(b + sm->hval[slot]), c);
                }
                __syncwarp();
                unsigned long long mine[4];
                mine[0] = sm->top[it][lane];
                mine[1] = sm->top[it][lane + 32];
                mine[2] = (lane < nb)      ? sm->cand[RR + lane]      : 0ull;
                mine[3] = (lane + 32 < nb) ? sm->cand[RR + lane + 32] : 0ull;
                const bool ext = nb > 64;
                for (int j = 0; j < nb; ++j) {
                    int col = key_idx(sm->cand[RR + j]);
                    if (key_idx(mine[0]) == col) mine[0] = 0ull;
                    if (key_idx(mine[1]) == col) mine[1] = 0ull;
                }
                const int nc = RR + nb;
                #pragma unroll
                for (int pp = 0; pp < 6; ++pp) {
                    unsigned long long b = mine[0];
                    if (mine[1] > b) b = mine[1];
                    if (mine[2] > b) b = mine[2];
                    if (mine[3] > b) b = mine[3];
                    if (ext)
                        for (int j = RR + 64 + lane; j < nc; j += 32) {
                            unsigned long long v = sm->cand[j];
                            if (v > b) b = v;
                        }
                    unsigned hi = (unsigned)(b >> 32);
                    unsigned himax = __reduce_max_sync(0xFFFFFFFFu, hi);
                    unsigned lo = (hi == himax) ? (unsigned)b : 0u;
                    unsigned lomax = __reduce_max_sync(0xFFFFFFFFu, lo);
                    unsigned long long win = ((unsigned long long)himax << 32) | lomax;
                    t[pp] = win;
                    #pragma unroll
                    for (int q = 0; q < 4; ++q) if (mine[q] == win) mine[q] = 0ull;
                    if (ext)
                        for (int j = RR + 64 + lane; j < nc; j += 32)
                            if (sm->cand[j] == win) sm->cand[j] = 0ull;
                }
            }

            const int next = (mode == 2) ? sm->srnd[it] : key_idx(t[0]);
            int myc = (mode != 2) ? key_idx(sm->top[it][lane]) : -1;
            unsigned mmask = __ballot_sync(0xFFFFFFFFu, myc == next);

            float hnew = 0.f;
            if (lane == 0) {
                unsigned key = ((unsigned)next << 13) | (unsigned)prev;
                int slot = hfind(sm, key);
                float base; bool have = false;
                if (slot >= 0) {
                    float b = sm->hbase[slot];
                    if (b == b) { base = b; have = true; }
                }
                if (!have) {
                    if (mode == 2)       base = sm->specR[it];
                    else if (mmask)      base = sm->spec[it][__ffs(mmask) - 1];
                    else                 base = __ldg(&W[(size_t)next * Nn + prev]);
                }
                float cur = base + ((slot >= 0) ? sm->hval[slot] : 0.f);
                float sp  = sm->s_spark[bkt];
                hnew = cur * 0.95f + sp * 0.05f;
                if (slot >= 0) {
                    sm->hbase[slot] = base;
                    sm->hval[slot] += hnew - cur;
                } else {
                    unsigned h = hash_h(key);
                    while (sm->hkey[h] != 0xFFFFFFFFu) h = (h + 1) & (HASHSZ - 1);
                    sm->hkey[h]  = key;
                    sm->hbase[h] = base;
                    sm->hval[h]  = hnew - base;
                    int li = sm->list_cnt; sm->list[li] = h; sm->list_cnt = li + 1;
                    unsigned bb = sm->row2b[next];
                    if (bb != 255u) {
                        int p = sm->bcnt[bb];
                        if (p < BCAP) sm->bent[bb][p] = (unsigned short)h;
                        sm->bcnt[bb] = p + 1;
                    }
                }
                unsigned bn = sm->row2b[next];
                if (bn != 255u) sm->s_spark[bn] = sm->sen[it] * 0.98f;
                sm->next_all[it] = next;
            }
            hnew = __shfl_sync(0xFFFFFFFFu, hnew, 0);

            // top-5 after Hebbian: only in-row element (prev,prev) can change
            unsigned long long top5[5];
            if (next == prev) {
                unsigned long long cnd[7];
                int cn = 0;
                #pragma unroll
                for (int q = 0; q < 6; ++q)
                    if (key_idx(t[q]) != prev) cnd[cn++] = t[q];
                cnd[cn++] = pack64(valkey(hnew), prev);
                for (int a = 1; a < cn; ++a) {
                    unsigned long long kx = cnd[a];
                    int b = a - 1;
                    while (b >= 0 && cnd[b] < kx) { cnd[b + 1] = cnd[b]; --b; }
                    cnd[b + 1] = kx;
                }
                #pragma unroll
                for (int q = 0; q < 5; ++q) top5[q] = cnd[q];
            } else {
                #pragma unroll
                for (int q = 0; q < 5; ++q) top5[q] = t[q];
            }

            // ripple: 35 additive updates across lanes
            for (int u = lane; u < 35; u += 32) {
                int r, c; float d;
                if (u < 5)       { r = prev;                c = key_idx(top5[u]);   d = 0.01f;  }
                else if (u < 10) { r = key_idx(top5[u-5]);  c = prev;               d = 0.005f; }
                else {
                    int a = (u - 10) / 5, b2 = (u - 10) % 5;
                    r = key_idx(top5[a]); c = key_idx(top5[b2]); d = 0.003f;
                }
                hadd(sm, r, c, d);
            }
            __syncwarp();
        }
    }
    __syncthreads();

    // ---- epilogue part 1: pos/energy/age (scan-exclusive outputs) ----
    if (tid < Kk) {
        float ed   = sm->sen[tid] * 0.98f;
        bool reset = ed < 0.05f;
        int pn = reset ? (tid % Nn) : sm->next_all[tid];
        out[tid]      = (float)pn;
        out[oE + tid] = reset ? 1.0f : ed;
        out[oA + tid] = (float)(reset ? 0 : (spark_age[tid] + 1));
    }

    // ---- wait for GEMV workers, then apply s/W overwrites ----
    if (tid == 0) {
        while (atomicAdd(&g_gemv_done, 0) < NWORK) __nanosleep(128);
    }
    __syncthreads();

    if (tid == 0) {
        // replay s writes in reference order (force, then sequential e_dec)
        for (int b = 0; b < Kk; ++b)
            if (spark_age[b] < 5) {
                int p = sm->spp[b];
                if (p >= 0 && p < Nn) out[oS + p] = 1.0f;
            }
        for (int it = 0; it < Kk; ++it)
            out[oS + sm->next_all[it]] = sm->sen[it] * 0.98f;
    }
    {
        int nl = sm->list_cnt;
        for (int j = tid; j < nl; j += 1024) {
            unsigned slot = sm->list[j];
            unsigned key  = sm->hkey[slot];
            int r = (int)(key >> 13), c = (int)(key & (Nn - 1));
            float b = sm->hbase[slot];
            if (b != b) b = __ldg(&W[(size_t)r * Nn + c]);
            float v = (b + sm->hval[slot]) * 0.999f;
            out[oW + (size_t)r * Nn + c] = fminf(fmaxf(v, -2.f), 2.f);
        }
    }
    __syncthreads();
    if (tid == 0) {                       // replay determinism
        g_spark_done = 0; g_gemv_done = 0; g_row_ctr = 0;
    }
}

// ---------------------------------------------------------------------------
// launch
// ---------------------------------------------------------------------------
extern "C" void kernel_launch(void* const* d_in, const int* in_sizes, int n_in,
                              void* d_out, int out_size)
{
    const float* W      = (const float*)d_in[0];
    const float* s      = (const float*)d_in[1];
    const float* noise  = (const float*)d_in[2];
    // d_in[3] = unif : unused (scalar gumbel shift doesn't change argmax)
    const float* energy = (const float*)d_in[4];
    const int* spark_pos = (const int*)d_in[5];
    const int* spark_age = (const int*)d_in[6];
    const int* randint   = (const int*)d_in[7];
    const int* step      = (n_in > 8) ? (const int*)d_in[8] : nullptr;
    float* out = (float*)d_out;

    (void)in_sizes; (void)out_size;

    cudaFuncSetAttribute(fused_kernel, cudaFuncAttributeMaxDynamicSharedMemorySize,
                         (int)sizeof(SS));
    fused_kernel<<<GRIDSZ, 1024, sizeof(SS)>>>(W, s, noise, energy, spark_pos,
                                               spark_age, randint, step, out);
}